// round 13
// baseline (speedup 1.0000x reference)
#include <cuda_runtime.h>
#include <cuda_fp16.h>
#include <cstdint>
#include <cstdio>

#define HDIM 64

static const int NMAX = 100000;
static const int EMAX = 1600000;
static const int SCANB = 1024;
static const int NBLK = (NMAX + SCANB - 1) / SCANB;   // 98

// ---------------- device scratch (allocation-free rule) ----------------
__device__ __align__(16) int    g_cnt[NMAX];
__device__ __align__(16) int    g_rowptr[NMAX];
__device__ __align__(16) int    g_cursor[NMAX];
__device__ __align__(16) int    g_bsum[NBLK];
__device__ __align__(16) int    g_boff[NBLK];
__device__ __align__(16) float  g_dinv[NMAX];
__device__ __align__(16) int    g_csr_src[EMAX];
__device__ __align__(16) float  g_csr_norm[EMAX];
__device__ __align__(16) float  g_ht[(size_t)NMAX * HDIM];
__device__ __align__(16) __half g_ht16[(size_t)NMAX * HDIM];   // fp16 copy for gathers
__device__ __align__(16) float  g_bufA[(size_t)NMAX * HDIM];
__device__ __align__(16) float  g_bufB[(size_t)NMAX * HDIM];

// ---------------- prep: degree histogram, dinv, scan, CSR scatter ----------------
__global__ void hist_kernel(const int* __restrict__ ei, int E) {
    int e = blockIdx.x * blockDim.x + threadIdx.x;
    if (e >= E) return;
    atomicAdd(&g_cnt[ei[(size_t)E + e]], 1);
}

// block-level inclusive scan -> exclusive partials + block sums; also dinv
__global__ void scan1_kernel(int N) {
    __shared__ int s[SCANB];
    int t = threadIdx.x;
    int i = blockIdx.x * SCANB + t;
    int v = (i < N) ? g_cnt[i] : 0;
    if (i < N) g_dinv[i] = rsqrtf((float)v + 1.0f);  // +1 = self loop
    s[t] = v;
    __syncthreads();
#pragma unroll
    for (int off = 1; off < SCANB; off <<= 1) {
        int a = (t >= off) ? s[t - off] : 0;
        __syncthreads();
        s[t] += a;
        __syncthreads();
    }
    if (i < N) g_rowptr[i] = s[t] - v;   // exclusive
    if (t == SCANB - 1) g_bsum[blockIdx.x] = s[t];
}

// single-block parallel scan of block sums (nb <= 128)
__global__ void scan2_kernel(int nb) {
    __shared__ int s[128];
    int t = threadIdx.x;
    int v = (t < nb) ? g_bsum[t] : 0;
    s[t] = v;
    __syncthreads();
#pragma unroll
    for (int off = 1; off < 128; off <<= 1) {
        int a = (t >= off) ? s[t - off] : 0;
        __syncthreads();
        s[t] += a;
        __syncthreads();
    }
    if (t < nb) g_boff[t] = s[t] - v;    // exclusive
}

__global__ void scan3_kernel(int N) {
    int i = blockIdx.x * blockDim.x + threadIdx.x;
    if (i >= N) return;
    int r = g_rowptr[i] + g_boff[i >> 10];
    g_rowptr[i] = r;
    g_cursor[i] = r;
}

__global__ void scatter_csr_kernel(const int* __restrict__ ei, int E) {
    int e = blockIdx.x * blockDim.x + threadIdx.x;
    if (e >= E) return;
    int s = ei[e];
    int d = ei[(size_t)E + e];
    int pos = atomicAdd(&g_cursor[d], 1);
    g_csr_src[pos]  = s;
    g_csr_norm[pos] = g_dinv[s] * g_dinv[d];
}

// ---------------- GEMM: HT = act(X) @ W  (packed fp32x2 FMA, col-pair form)
// BM=32 rows x 64 cols per block, 128 threads, 4 rows x 8 cols (4 f32x2 pairs) each.
// Epilogue writes fp32 HT (self-loop path) + fp16 HT16 (gather path).
template <int DIN, bool RELU_IN>
__global__ void __launch_bounds__(128) gemm_kernel(const float* __restrict__ X,
                                                   const float* __restrict__ W,
                                                   float* __restrict__ HT,
                                                   __half* __restrict__ HT16,
                                                   int N) {
    __shared__ __align__(16) float Xs[16][32];
    __shared__ __align__(16) float Ws[16][64];

    const int t   = threadIdx.x;      // 0..127
    const int rg  = t >> 4;           // 0..7  (row group of 4)
    const int cg  = t & 15;           // 0..15 (col group of 4)
    const int row0 = blockIdx.x * 32;

    unsigned long long acc2[4][2];
#pragma unroll
    for (int i = 0; i < 4; i++) { acc2[i][0] = 0ull; acc2[i][1] = 0ull; }

    for (int k0 = 0; k0 < DIN; k0 += 16) {
        // load X tile: 32 rows x 16 k (each thread: one float4)
        {
            int r  = t >> 2;          // 0..31
            int kk = (t & 3) * 4;     // 0,4,8,12
            int grow = row0 + r;
            float4 v = make_float4(0.f, 0.f, 0.f, 0.f);
            if (grow < N)
                v = *(const float4*)&X[(size_t)grow * DIN + k0 + kk];
            if (RELU_IN) {
                v.x = fmaxf(v.x, 0.f); v.y = fmaxf(v.y, 0.f);
                v.z = fmaxf(v.z, 0.f); v.w = fmaxf(v.w, 0.f);
            }
            Xs[kk + 0][r] = v.x;
            Xs[kk + 1][r] = v.y;
            Xs[kk + 2][r] = v.z;
            Xs[kk + 3][r] = v.w;
        }
        // load W tile: 16 x 64 floats (each thread: two float4)
        {
#pragma unroll
            for (int i = 0; i < 2; i++) {
                int idx = t + i * 128;        // float4 index, 0..255
                int kk  = idx >> 4;           // 0..15
                int c   = (idx & 15) * 4;     // 0..60
                float4 w = *(const float4*)&W[(size_t)(k0 + kk) * HDIM + c];
                *(float4*)&Ws[kk][c] = w;
            }
        }
        __syncthreads();

#pragma unroll
        for (int kk = 0; kk < 16; kk++) {
            float4 xv = *(const float4*)&Xs[kk][rg * 4];
            ulonglong2 wv = *(const ulonglong2*)&Ws[kk][cg * 4]; // {w0,w1},{w2,w3}
            unsigned int xb[4] = {__float_as_uint(xv.x), __float_as_uint(xv.y),
                                  __float_as_uint(xv.z), __float_as_uint(xv.w)};
#pragma unroll
            for (int i = 0; i < 4; i++) {
                unsigned long long xp;
                asm("mov.b64 %0, {%1, %1};" : "=l"(xp) : "r"(xb[i]));
                asm("fma.rn.f32x2 %0, %1, %2, %0;" : "+l"(acc2[i][0]) : "l"(xp), "l"(wv.x));
                asm("fma.rn.f32x2 %0, %1, %2, %0;" : "+l"(acc2[i][1]) : "l"(xp), "l"(wv.y));
            }
        }
        __syncthreads();
    }

    // epilogue: write fp32 HT and fp16 HT16
#pragma unroll
    for (int i = 0; i < 4; i++) {
        int grow = row0 + rg * 4 + i;
        if (grow < N) {
            unsigned int u0, u1, u2, u3;
            asm("mov.b64 {%0, %1}, %2;" : "=r"(u0), "=r"(u1) : "l"(acc2[i][0]));
            asm("mov.b64 {%0, %1}, %2;" : "=r"(u2), "=r"(u3) : "l"(acc2[i][1]));
            float f0 = __uint_as_float(u0), f1 = __uint_as_float(u1);
            float f2 = __uint_as_float(u2), f3 = __uint_as_float(u3);
            *(float4*)&HT[(size_t)grow * HDIM + cg * 4] = make_float4(f0, f1, f2, f3);
            __half2 p0 = __floats2half2_rn(f0, f1);
            __half2 p1 = __floats2half2_rn(f2, f3);
            uint2 hv;
            hv.x = *(unsigned int*)&p0;
            hv.y = *(unsigned int*)&p1;
            *(uint2*)&HT16[(size_t)grow * HDIM + cg * 4] = hv;
        }
    }
}

// ---------------- aggregate: OUT[d] = bias + HT[d]*dinv[d]^2 + sum_e HT16[src_e]*norm_e
// 16 threads per node, each owns 4 of the 64 columns. Gathers are fp16 (8B/lane).
__global__ void aggregate_kernel(const float* __restrict__ HT,
                                 const __half* __restrict__ HT16,
                                 const float* __restrict__ bias,
                                 float* __restrict__ OUT,
                                 int N) {
    int idx  = blockIdx.x * blockDim.x + threadIdx.x;
    int node = idx >> 4;
    int lane = idx & 15;
    if (node >= N) return;

    int start = g_rowptr[node];
    int cnt   = g_cnt[node];

    float4 a0 = make_float4(0.f, 0.f, 0.f, 0.f);
    float4 a1 = make_float4(0.f, 0.f, 0.f, 0.f);

    int i = 0;
    for (; i + 2 <= cnt; i += 2) {
        int e0 = start + i, e1 = start + i + 1;
        int s0 = g_csr_src[e0], s1 = g_csr_src[e1];
        float n0 = g_csr_norm[e0], n1 = g_csr_norm[e1];
        uint2 r0 = *(const uint2*)&HT16[(size_t)s0 * HDIM + lane * 4];
        uint2 r1 = *(const uint2*)&HT16[(size_t)s1 * HDIM + lane * 4];
        float2 v0a = __half22float2(*(__half2*)&r0.x);
        float2 v0b = __half22float2(*(__half2*)&r0.y);
        float2 v1a = __half22float2(*(__half2*)&r1.x);
        float2 v1b = __half22float2(*(__half2*)&r1.y);
        a0.x += v0a.x * n0; a0.y += v0a.y * n0; a0.z += v0b.x * n0; a0.w += v0b.y * n0;
        a1.x += v1a.x * n1; a1.y += v1a.y * n1; a1.z += v1b.x * n1; a1.w += v1b.y * n1;
    }
    if (i < cnt) {
        int e0 = start + i;
        int s0 = g_csr_src[e0];
        float n0 = g_csr_norm[e0];
        uint2 r0 = *(const uint2*)&HT16[(size_t)s0 * HDIM + lane * 4];
        float2 v0a = __half22float2(*(__half2*)&r0.x);
        float2 v0b = __half22float2(*(__half2*)&r0.y);
        a0.x += v0a.x * n0; a0.y += v0a.y * n0; a0.z += v0b.x * n0; a0.w += v0b.y * n0;
    }
    a0.x += a1.x; a0.y += a1.y; a0.z += a1.z; a0.w += a1.w;

    float di = g_dinv[node];
    float d2 = di * di;
    float4 h  = *(const float4*)&HT[(size_t)node * HDIM + lane * 4];
    float4 bb = *(const float4*)&bias[lane * 4];
    float4 o;
    o.x = bb.x + h.x * d2 + a0.x;
    o.y = bb.y + h.y * d2 + a0.y;
    o.z = bb.z + h.z * d2 + a0.z;
    o.w = bb.w + h.w * d2 + a0.w;
    *(float4*)&OUT[(size_t)node * HDIM + lane * 4] = o;
}

// ---------------- aggregate3 fused with relu + FC(64->2) + log_softmax ----------------
__global__ void aggregate_fc_kernel(const float* __restrict__ HT,
                                    const __half* __restrict__ HT16,
                                    const float* __restrict__ bias,
                                    const float* __restrict__ Wfc,
                                    const float* __restrict__ bfc,
                                    float* __restrict__ out,
                                    int N) {
    int idx  = blockIdx.x * blockDim.x + threadIdx.x;
    int node = idx >> 4;
    int lane = idx & 15;
    if (node >= N) return;

    int start = g_rowptr[node];
    int cnt   = g_cnt[node];

    float4 a0 = make_float4(0.f, 0.f, 0.f, 0.f);
    float4 a1 = make_float4(0.f, 0.f, 0.f, 0.f);

    int i = 0;
    for (; i + 2 <= cnt; i += 2) {
        int e0 = start + i, e1 = start + i + 1;
        int s0 = g_csr_src[e0], s1 = g_csr_src[e1];
        float n0 = g_csr_norm[e0], n1 = g_csr_norm[e1];
        uint2 r0 = *(const uint2*)&HT16[(size_t)s0 * HDIM + lane * 4];
        uint2 r1 = *(const uint2*)&HT16[(size_t)s1 * HDIM + lane * 4];
        float2 v0a = __half22float2(*(__half2*)&r0.x);
        float2 v0b = __half22float2(*(__half2*)&r0.y);
        float2 v1a = __half22float2(*(__half2*)&r1.x);
        float2 v1b = __half22float2(*(__half2*)&r1.y);
        a0.x += v0a.x * n0; a0.y += v0a.y * n0; a0.z += v0b.x * n0; a0.w += v0b.y * n0;
        a1.x += v1a.x * n1; a1.y += v1a.y * n1; a1.z += v1b.x * n1; a1.w += v1b.y * n1;
    }
    if (i < cnt) {
        int e0 = start + i;
        int s0 = g_csr_src[e0];
        float n0 = g_csr_norm[e0];
        uint2 r0 = *(const uint2*)&HT16[(size_t)s0 * HDIM + lane * 4];
        float2 v0a = __half22float2(*(__half2*)&r0.x);
        float2 v0b = __half22float2(*(__half2*)&r0.y);
        a0.x += v0a.x * n0; a0.y += v0a.y * n0; a0.z += v0b.x * n0; a0.w += v0b.y * n0;
    }
    a0.x += a1.x; a0.y += a1.y; a0.z += a1.z; a0.w += a1.w;

    float di = g_dinv[node];
    float d2 = di * di;
    float4 h  = *(const float4*)&HT[(size_t)node * HDIM + lane * 4];
    float4 bb = *(const float4*)&bias[lane * 4];
    // layer-3 output features for this lane's 4 columns, after relu
    float f0 = fmaxf(bb.x + h.x * d2 + a0.x, 0.f);
    float f1 = fmaxf(bb.y + h.y * d2 + a0.y, 0.f);
    float f2 = fmaxf(bb.z + h.z * d2 + a0.z, 0.f);
    float f3 = fmaxf(bb.w + h.w * d2 + a0.w, 0.f);

    // partial logits from this lane's 4 columns
    int c0 = lane * 4;
    float4 w0 = *(const float4*)&Wfc[(c0 + 0) * 2];
    float4 w1 = *(const float4*)&Wfc[(c0 + 2) * 2];
    float l0 = f0 * w0.x + f1 * w0.z + f2 * w1.x + f3 * w1.z;
    float l1 = f0 * w0.y + f1 * w0.w + f2 * w1.y + f3 * w1.w;

    // reduce across the 16-lane group (aligned within warp)
#pragma unroll
    for (int off = 8; off > 0; off >>= 1) {
        l0 += __shfl_down_sync(0xffffffffu, l0, off);
        l1 += __shfl_down_sync(0xffffffffu, l1, off);
    }
    if (lane == 0) {
        l0 += bfc[0];
        l1 += bfc[1];
        float m = fmaxf(l0, l1);
        float lse = m + logf(expf(l0 - m) + expf(l1 - m));
        out[(size_t)node * 2 + 0] = l0 - lse;
        out[(size_t)node * 2 + 1] = l1 - lse;
    }
}

// ---------------- launch ----------------
extern "C" void kernel_launch(void* const* d_in, const int* in_sizes, int n_in,
                              void* d_out, int out_size) {
    const float* x   = (const float*)d_in[0];
    const int*   ei  = (const int*)d_in[1];   // int32 (JAX x64 disabled)
    const float* W1  = (const float*)d_in[2];
    const float* b1  = (const float*)d_in[3];
    const float* W2  = (const float*)d_in[4];
    const float* b2  = (const float*)d_in[5];
    const float* W3  = (const float*)d_in[6];
    const float* b3  = (const float*)d_in[7];
    const float* Wfc = (const float*)d_in[8];
    const float* bfc = (const float*)d_in[9];

    const int Hh = in_sizes[3];            // 64
    const int D  = in_sizes[2] / Hh;       // 128
    const int N  = in_sizes[0] / D;        // 100000
    const int E  = in_sizes[1] / 2;        // 1600000

    float *ht, *bufA, *bufB;
    __half* ht16;
    int* cnt;
    cudaGetSymbolAddress((void**)&ht,   g_ht);
    cudaGetSymbolAddress((void**)&ht16, g_ht16);
    cudaGetSymbolAddress((void**)&bufA, g_bufA);
    cudaGetSymbolAddress((void**)&bufB, g_bufB);
    cudaGetSymbolAddress((void**)&cnt,  g_cnt);

    // Lazy one-time stream/event creation (first call is the uncaptured
    // correctness run; resources are reused inside the captured graph).
    static cudaStream_t sPrep = nullptr;
    static cudaEvent_t  eFork = nullptr, eJoin = nullptr;
    if (sPrep == nullptr) {
        cudaStreamCreateWithFlags(&sPrep, cudaStreamNonBlocking);
        cudaEventCreateWithFlags(&eFork, cudaEventDisableTiming);
        cudaEventCreateWithFlags(&eJoin, cudaEventDisableTiming);
    }

    const int nb = (N + SCANB - 1) / SCANB;
    const int gblocks = (N + 31) / 32;
    const int ablocks = (N * 16 + 255) / 256;

    // Fork: CSR build on sPrep, concurrent with gemm1 on the main stream.
    cudaEventRecord(eFork, 0);
    cudaStreamWaitEvent(sPrep, eFork, 0);

    // --- prep branch (independent of gemm1) ---
    cudaMemsetAsync(cnt, 0, (size_t)N * sizeof(int), sPrep);
    hist_kernel<<<(E + 255) / 256, 256, 0, sPrep>>>(ei, E);
    scan1_kernel<<<nb, SCANB, 0, sPrep>>>(N);
    scan2_kernel<<<1, 128, 0, sPrep>>>(nb);
    scan3_kernel<<<(N + 255) / 256, 256, 0, sPrep>>>(N);
    scatter_csr_kernel<<<(E + 255) / 256, 256, 0, sPrep>>>(ei, E);
    cudaEventRecord(eJoin, sPrep);

    // --- main branch ---
    gemm_kernel<128, false><<<gblocks, 128>>>(x, W1, ht, ht16, N);

    // Join: aggregate1 needs both gemm1 (main) and CSR (sPrep).
    cudaStreamWaitEvent(0, eJoin, 0);

    aggregate_kernel<<<ablocks, 256>>>(ht, ht16, b1, bufA, N);
    // layer 2
    gemm_kernel<64, true><<<gblocks, 128>>>(bufA, W2, ht, ht16, N);
    aggregate_kernel<<<ablocks, 256>>>(ht, ht16, b2, bufB, N);
    // layer 3 (aggregate fused with FC + log_softmax)
    gemm_kernel<64, true><<<gblocks, 128>>>(bufB, W3, ht, ht16, N);
    aggregate_fc_kernel<<<ablocks, 256>>>(ht, ht16, b3, Wfc, bfc, (float*)d_out, N);
}

// round 17
// speedup vs baseline: 1.0962x; 1.0962x over previous
#include <cuda_runtime.h>
#include <cuda_fp16.h>
#include <cstdint>
#include <cstdio>

#define HDIM 64

static const int NMAX = 100000;
static const int EMAX = 1600000;
static const int SCANB = 1024;
static const int NBLK = (NMAX + SCANB - 1) / SCANB;   // 98

// ---------------- device scratch (allocation-free rule) ----------------
__device__ __align__(16) int    g_cnt[NMAX];
__device__ __align__(16) int    g_rowptr[NMAX];
__device__ __align__(16) int    g_cursor[NMAX];
__device__ __align__(16) int    g_bsum[NBLK];
__device__ __align__(16) int    g_boff[NBLK];
__device__ __align__(16) float  g_dinv[NMAX];
__device__ __align__(16) int    g_csr_src[EMAX];
__device__ __align__(16) float  g_csr_norm[EMAX];
__device__ __align__(16) __half g_ht16[(size_t)NMAX * HDIM];   // fp16 hidden (gather + self)
__device__ __align__(16) float  g_bufA[(size_t)NMAX * HDIM];
__device__ __align__(16) float  g_bufB[(size_t)NMAX * HDIM];

// ---------------- prep: degree histogram, dinv, scan, CSR scatter ----------------
__global__ void hist_kernel(const int* __restrict__ ei, int E) {
    int e = blockIdx.x * blockDim.x + threadIdx.x;
    if (e >= E) return;
    atomicAdd(&g_cnt[ei[(size_t)E + e]], 1);
}

// block-level inclusive scan -> exclusive partials + block sums; also dinv
__global__ void scan1_kernel(int N) {
    __shared__ int s[SCANB];
    int t = threadIdx.x;
    int i = blockIdx.x * SCANB + t;
    int v = (i < N) ? g_cnt[i] : 0;
    if (i < N) g_dinv[i] = rsqrtf((float)v + 1.0f);  // +1 = self loop
    s[t] = v;
    __syncthreads();
#pragma unroll
    for (int off = 1; off < SCANB; off <<= 1) {
        int a = (t >= off) ? s[t - off] : 0;
        __syncthreads();
        s[t] += a;
        __syncthreads();
    }
    if (i < N) g_rowptr[i] = s[t] - v;   // exclusive
    if (t == SCANB - 1) g_bsum[blockIdx.x] = s[t];
}

// single-block parallel scan of block sums (nb <= 128)
__global__ void scan2_kernel(int nb) {
    __shared__ int s[128];
    int t = threadIdx.x;
    int v = (t < nb) ? g_bsum[t] : 0;
    s[t] = v;
    __syncthreads();
#pragma unroll
    for (int off = 1; off < 128; off <<= 1) {
        int a = (t >= off) ? s[t - off] : 0;
        __syncthreads();
        s[t] += a;
        __syncthreads();
    }
    if (t < nb) g_boff[t] = s[t] - v;    // exclusive
}

__global__ void scan3_kernel(int N) {
    int i = blockIdx.x * blockDim.x + threadIdx.x;
    if (i >= N) return;
    int r = g_rowptr[i] + g_boff[i >> 10];
    g_rowptr[i] = r;
    g_cursor[i] = r;
}

__global__ void scatter_csr_kernel(const int* __restrict__ ei, int E) {
    int e = blockIdx.x * blockDim.x + threadIdx.x;
    if (e >= E) return;
    int s = ei[e];
    int d = ei[(size_t)E + e];
    int pos = atomicAdd(&g_cursor[d], 1);
    g_csr_src[pos]  = s;
    g_csr_norm[pos] = g_dinv[s] * g_dinv[d];
}

// ---------------- GEMM: HT16 = act(X) @ W  (packed fp32x2 FMA, col-pair form)
// BM=32 rows x 64 cols per block, 128 threads, 4 rows x 8 cols (4 f32x2 pairs) each.
// Epilogue writes fp16 only.
template <int DIN, bool RELU_IN>
__global__ void __launch_bounds__(128) gemm_kernel(const float* __restrict__ X,
                                                   const float* __restrict__ W,
                                                   __half* __restrict__ HT16,
                                                   int N) {
    __shared__ __align__(16) float Xs[16][32];
    __shared__ __align__(16) float Ws[16][64];

    const int t   = threadIdx.x;      // 0..127
    const int rg  = t >> 4;           // 0..7  (row group of 4)
    const int cg  = t & 15;           // 0..15 (col group of 4)
    const int row0 = blockIdx.x * 32;

    unsigned long long acc2[4][2];
#pragma unroll
    for (int i = 0; i < 4; i++) { acc2[i][0] = 0ull; acc2[i][1] = 0ull; }

    for (int k0 = 0; k0 < DIN; k0 += 16) {
        // load X tile: 32 rows x 16 k (each thread: one float4)
        {
            int r  = t >> 2;          // 0..31
            int kk = (t & 3) * 4;     // 0,4,8,12
            int grow = row0 + r;
            float4 v = make_float4(0.f, 0.f, 0.f, 0.f);
            if (grow < N)
                v = *(const float4*)&X[(size_t)grow * DIN + k0 + kk];
            if (RELU_IN) {
                v.x = fmaxf(v.x, 0.f); v.y = fmaxf(v.y, 0.f);
                v.z = fmaxf(v.z, 0.f); v.w = fmaxf(v.w, 0.f);
            }
            Xs[kk + 0][r] = v.x;
            Xs[kk + 1][r] = v.y;
            Xs[kk + 2][r] = v.z;
            Xs[kk + 3][r] = v.w;
        }
        // load W tile: 16 x 64 floats (each thread: two float4)
        {
#pragma unroll
            for (int i = 0; i < 2; i++) {
                int idx = t + i * 128;        // float4 index, 0..255
                int kk  = idx >> 4;           // 0..15
                int c   = (idx & 15) * 4;     // 0..60
                float4 w = *(const float4*)&W[(size_t)(k0 + kk) * HDIM + c];
                *(float4*)&Ws[kk][c] = w;
            }
        }
        __syncthreads();

#pragma unroll
        for (int kk = 0; kk < 16; kk++) {
            float4 xv = *(const float4*)&Xs[kk][rg * 4];
            ulonglong2 wv = *(const ulonglong2*)&Ws[kk][cg * 4]; // {w0,w1},{w2,w3}
            unsigned int xb[4] = {__float_as_uint(xv.x), __float_as_uint(xv.y),
                                  __float_as_uint(xv.z), __float_as_uint(xv.w)};
#pragma unroll
            for (int i = 0; i < 4; i++) {
                unsigned long long xp;
                asm("mov.b64 %0, {%1, %1};" : "=l"(xp) : "r"(xb[i]));
                asm("fma.rn.f32x2 %0, %1, %2, %0;" : "+l"(acc2[i][0]) : "l"(xp), "l"(wv.x));
                asm("fma.rn.f32x2 %0, %1, %2, %0;" : "+l"(acc2[i][1]) : "l"(xp), "l"(wv.y));
            }
        }
        __syncthreads();
    }

    // epilogue: write fp16 HT16 only
#pragma unroll
    for (int i = 0; i < 4; i++) {
        int grow = row0 + rg * 4 + i;
        if (grow < N) {
            unsigned int u0, u1, u2, u3;
            asm("mov.b64 {%0, %1}, %2;" : "=r"(u0), "=r"(u1) : "l"(acc2[i][0]));
            asm("mov.b64 {%0, %1}, %2;" : "=r"(u2), "=r"(u3) : "l"(acc2[i][1]));
            __half2 p0 = __floats2half2_rn(__uint_as_float(u0), __uint_as_float(u1));
            __half2 p1 = __floats2half2_rn(__uint_as_float(u2), __uint_as_float(u3));
            uint2 hv;
            hv.x = *(unsigned int*)&p0;
            hv.y = *(unsigned int*)&p1;
            *(uint2*)&HT16[(size_t)grow * HDIM + cg * 4] = hv;
        }
    }
}

// helper: accumulate 8 halves (uint4) * n into 8 floats
__device__ __forceinline__ void acc8(float* a, uint4 r, float n) {
    float2 p0 = __half22float2(*(__half2*)&r.x);
    float2 p1 = __half22float2(*(__half2*)&r.y);
    float2 p2 = __half22float2(*(__half2*)&r.z);
    float2 p3 = __half22float2(*(__half2*)&r.w);
    a[0] += p0.x * n; a[1] += p0.y * n;
    a[2] += p1.x * n; a[3] += p1.y * n;
    a[4] += p2.x * n; a[5] += p2.y * n;
    a[6] += p3.x * n; a[7] += p3.y * n;
}

// ---------------- aggregate: OUT[d] = bias + HT16[d]*dinv[d]^2 + sum_e HT16[src_e]*norm_e
// 8 threads per node, each owns 8 of the 64 columns (16B fp16 per lane per gather).
__global__ void aggregate_kernel(const __half* __restrict__ HT16,
                                 const float* __restrict__ bias,
                                 float* __restrict__ OUT,
                                 int N) {
    int idx  = blockIdx.x * blockDim.x + threadIdx.x;
    int node = idx >> 3;
    int lane = idx & 7;
    if (node >= N) return;

    int start = g_rowptr[node];
    int cnt   = g_cnt[node];

    float a0[8] = {}, a1[8] = {};

    int i = 0;
    for (; i + 2 <= cnt; i += 2) {
        int e0 = start + i, e1 = start + i + 1;
        int s0 = g_csr_src[e0], s1 = g_csr_src[e1];
        float n0 = g_csr_norm[e0], n1 = g_csr_norm[e1];
        uint4 r0 = *(const uint4*)&HT16[(size_t)s0 * HDIM + lane * 8];
        uint4 r1 = *(const uint4*)&HT16[(size_t)s1 * HDIM + lane * 8];
        acc8(a0, r0, n0);
        acc8(a1, r1, n1);
    }
    if (i < cnt) {
        int e0 = start + i;
        int s0 = g_csr_src[e0];
        float n0 = g_csr_norm[e0];
        uint4 r0 = *(const uint4*)&HT16[(size_t)s0 * HDIM + lane * 8];
        acc8(a0, r0, n0);
    }
#pragma unroll
    for (int j = 0; j < 8; j++) a0[j] += a1[j];

    float di = g_dinv[node];
    float d2 = di * di;
    uint4 hr = *(const uint4*)&HT16[(size_t)node * HDIM + lane * 8];
    float h[8] = {};
    acc8(h, hr, d2);   // h = HT16[node] * d2
    float4 bb0 = *(const float4*)&bias[lane * 8];
    float4 bb1 = *(const float4*)&bias[lane * 8 + 4];
    float4 o0, o1;
    o0.x = bb0.x + h[0] + a0[0];
    o0.y = bb0.y + h[1] + a0[1];
    o0.z = bb0.z + h[2] + a0[2];
    o0.w = bb0.w + h[3] + a0[3];
    o1.x = bb1.x + h[4] + a0[4];
    o1.y = bb1.y + h[5] + a0[5];
    o1.z = bb1.z + h[6] + a0[6];
    o1.w = bb1.w + h[7] + a0[7];
    *(float4*)&OUT[(size_t)node * HDIM + lane * 8]     = o0;
    *(float4*)&OUT[(size_t)node * HDIM + lane * 8 + 4] = o1;
}

// ---------------- aggregate3 fused with relu + FC(64->2) + log_softmax ----------------
__global__ void aggregate_fc_kernel(const __half* __restrict__ HT16,
                                    const float* __restrict__ bias,
                                    const float* __restrict__ Wfc,
                                    const float* __restrict__ bfc,
                                    float* __restrict__ out,
                                    int N) {
    int idx  = blockIdx.x * blockDim.x + threadIdx.x;
    int node = idx >> 3;
    int lane = idx & 7;
    if (node >= N) return;

    int start = g_rowptr[node];
    int cnt   = g_cnt[node];

    float a0[8] = {}, a1[8] = {};

    int i = 0;
    for (; i + 2 <= cnt; i += 2) {
        int e0 = start + i, e1 = start + i + 1;
        int s0 = g_csr_src[e0], s1 = g_csr_src[e1];
        float n0 = g_csr_norm[e0], n1 = g_csr_norm[e1];
        uint4 r0 = *(const uint4*)&HT16[(size_t)s0 * HDIM + lane * 8];
        uint4 r1 = *(const uint4*)&HT16[(size_t)s1 * HDIM + lane * 8];
        acc8(a0, r0, n0);
        acc8(a1, r1, n1);
    }
    if (i < cnt) {
        int e0 = start + i;
        int s0 = g_csr_src[e0];
        float n0 = g_csr_norm[e0];
        uint4 r0 = *(const uint4*)&HT16[(size_t)s0 * HDIM + lane * 8];
        acc8(a0, r0, n0);
    }
#pragma unroll
    for (int j = 0; j < 8; j++) a0[j] += a1[j];

    float di = g_dinv[node];
    float d2 = di * di;
    uint4 hr = *(const uint4*)&HT16[(size_t)node * HDIM + lane * 8];
    float h[8] = {};
    acc8(h, hr, d2);
    float4 bb0 = *(const float4*)&bias[lane * 8];
    float4 bb1 = *(const float4*)&bias[lane * 8 + 4];
    float f[8];
    f[0] = fmaxf(bb0.x + h[0] + a0[0], 0.f);
    f[1] = fmaxf(bb0.y + h[1] + a0[1], 0.f);
    f[2] = fmaxf(bb0.z + h[2] + a0[2], 0.f);
    f[3] = fmaxf(bb0.w + h[3] + a0[3], 0.f);
    f[4] = fmaxf(bb1.x + h[4] + a0[4], 0.f);
    f[5] = fmaxf(bb1.y + h[5] + a0[5], 0.f);
    f[6] = fmaxf(bb1.z + h[6] + a0[6], 0.f);
    f[7] = fmaxf(bb1.w + h[7] + a0[7], 0.f);

    // partial logits from this lane's 8 columns: Wfc is [64][2] row-major
    int c0 = lane * 8;
    float l0 = 0.f, l1 = 0.f;
#pragma unroll
    for (int j = 0; j < 4; j++) {
        float4 w = *(const float4*)&Wfc[(c0 + 2 * j) * 2];  // {W[c][0],W[c][1],W[c+1][0],W[c+1][1]}
        l0 += f[2 * j] * w.x + f[2 * j + 1] * w.z;
        l1 += f[2 * j] * w.y + f[2 * j + 1] * w.w;
    }

    // reduce across the 8-lane group (aligned within warp)
#pragma unroll
    for (int off = 4; off > 0; off >>= 1) {
        l0 += __shfl_down_sync(0xffffffffu, l0, off);
        l1 += __shfl_down_sync(0xffffffffu, l1, off);
    }
    if (lane == 0) {
        l0 += bfc[0];
        l1 += bfc[1];
        float m = fmaxf(l0, l1);
        float lse = m + logf(expf(l0 - m) + expf(l1 - m));
        out[(size_t)node * 2 + 0] = l0 - lse;
        out[(size_t)node * 2 + 1] = l1 - lse;
    }
}

// ---------------- launch ----------------
extern "C" void kernel_launch(void* const* d_in, const int* in_sizes, int n_in,
                              void* d_out, int out_size) {
    const float* x   = (const float*)d_in[0];
    const int*   ei  = (const int*)d_in[1];   // int32 (JAX x64 disabled)
    const float* W1  = (const float*)d_in[2];
    const float* b1  = (const float*)d_in[3];
    const float* W2  = (const float*)d_in[4];
    const float* b2  = (const float*)d_in[5];
    const float* W3  = (const float*)d_in[6];
    const float* b3  = (const float*)d_in[7];
    const float* Wfc = (const float*)d_in[8];
    const float* bfc = (const float*)d_in[9];

    const int Hh = in_sizes[3];            // 64
    const int D  = in_sizes[2] / Hh;       // 128
    const int N  = in_sizes[0] / D;        // 100000
    const int E  = in_sizes[1] / 2;        // 1600000

    float *bufA, *bufB;
    __half* ht16;
    int* cnt;
    cudaGetSymbolAddress((void**)&ht16, g_ht16);
    cudaGetSymbolAddress((void**)&bufA, g_bufA);
    cudaGetSymbolAddress((void**)&bufB, g_bufB);
    cudaGetSymbolAddress((void**)&cnt,  g_cnt);

    // Lazy one-time stream/event creation (first call is the uncaptured
    // correctness run; resources are reused inside the captured graph).
    static cudaStream_t sPrep = nullptr;
    static cudaEvent_t  eFork = nullptr, eJoin = nullptr;
    if (sPrep == nullptr) {
        cudaStreamCreateWithFlags(&sPrep, cudaStreamNonBlocking);
        cudaEventCreateWithFlags(&eFork, cudaEventDisableTiming);
        cudaEventCreateWithFlags(&eJoin, cudaEventDisableTiming);
    }

    const int nb = (N + SCANB - 1) / SCANB;
    const int gblocks = (N + 31) / 32;
    const int ablocks = (N * 8 + 255) / 256;

    // Fork: CSR build on sPrep, concurrent with gemm1 on the main stream.
    cudaEventRecord(eFork, 0);
    cudaStreamWaitEvent(sPrep, eFork, 0);

    // --- prep branch (independent of gemm1) ---
    cudaMemsetAsync(cnt, 0, (size_t)N * sizeof(int), sPrep);
    hist_kernel<<<(E + 255) / 256, 256, 0, sPrep>>>(ei, E);
    scan1_kernel<<<nb, SCANB, 0, sPrep>>>(N);
    scan2_kernel<<<1, 128, 0, sPrep>>>(nb);
    scan3_kernel<<<(N + 255) / 256, 256, 0, sPrep>>>(N);
    scatter_csr_kernel<<<(E + 255) / 256, 256, 0, sPrep>>>(ei, E);
    cudaEventRecord(eJoin, sPrep);

    // --- main branch ---
    gemm_kernel<128, false><<<gblocks, 128>>>(x, W1, ht16, N);

    // Join: aggregate1 needs both gemm1 (main) and CSR (sPrep).
    cudaStreamWaitEvent(0, eJoin, 0);

    aggregate_kernel<<<ablocks, 256>>>(ht16, b1, bufA, N);
    // layer 2
    gemm_kernel<64, true><<<gblocks, 128>>>(bufA, W2, ht16, N);
    aggregate_kernel<<<ablocks, 256>>>(ht16, b2, bufB, N);
    // layer 3 (aggregate fused with FC + log_softmax)
    gemm_kernel<64, true><<<gblocks, 128>>>(bufB, W3, ht16, N);
    aggregate_fc_kernel<<<ablocks, 256>>>(ht16, b3, Wfc, bfc, (float*)d_out, N);
}